// round 2
// baseline (speedup 1.0000x reference)
#include <cuda_runtime.h>
#include <math.h>

// InputLayer: out[b,n,d] = LN_d( (x[b,n]*W[d] + bias[d]) * sqrt(1024) ) * gamma[d] + beta[d]
// Analytic LayerNorm: h is affine in a=x[b,n], so mean/var are closed-form in
// per-column stats of (W, bias). Hot kernel is pure FMA + vectorized stores.

#define SIZE 1024
#define QUADS (SIZE / 4)          // 256 threads per block, one float4 column slice each
#define RPB 64                    // rows per block
#define LN_EPS 1e-5f

__device__ float g_stats[5];      // meanW, meanB, varW, varB, covWB

// ---------------------------------------------------------------------------
// Stats kernel: one block, 1024 threads, double accumulation.
// ---------------------------------------------------------------------------
__global__ void il_stats_kernel(const float* __restrict__ W,
                                const float* __restrict__ B) {
    int tid = threadIdx.x;                 // 0..1023
    double w = (double)W[tid];
    double b = (double)B[tid];
    double v0 = w, v1 = b, v2 = w * w, v3 = b * b, v4 = w * b;

    __shared__ double sm[5][32];
    int lane = tid & 31, warp = tid >> 5;

    #pragma unroll
    for (int o = 16; o > 0; o >>= 1) {
        v0 += __shfl_down_sync(0xffffffffu, v0, o);
        v1 += __shfl_down_sync(0xffffffffu, v1, o);
        v2 += __shfl_down_sync(0xffffffffu, v2, o);
        v3 += __shfl_down_sync(0xffffffffu, v3, o);
        v4 += __shfl_down_sync(0xffffffffu, v4, o);
    }
    if (lane == 0) {
        sm[0][warp] = v0; sm[1][warp] = v1; sm[2][warp] = v2;
        sm[3][warp] = v3; sm[4][warp] = v4;
    }
    __syncthreads();
    if (tid == 0) {
        double s[5] = {0, 0, 0, 0, 0};
        for (int wI = 0; wI < 32; wI++)
            for (int k = 0; k < 5; k++) s[k] += sm[k][wI];
        double inv = 1.0 / (double)SIZE;
        double mw = s[0] * inv, mb = s[1] * inv;
        g_stats[0] = (float)mw;
        g_stats[1] = (float)mb;
        g_stats[2] = (float)(s[2] * inv - mw * mw);   // Var(W)
        g_stats[3] = (float)(s[3] * inv - mb * mb);   // Var(B)
        g_stats[4] = (float)(s[4] * inv - mw * mb);   // Cov(W,B)
    }
}

// ---------------------------------------------------------------------------
// Main kernel: grid = nrows/RPB blocks of 256 threads.
// Thread q keeps (W,b,gamma,beta)[4q..4q+3] in registers, loops over RPB rows,
// 2 FMAs + 1 STG.128 per row. Pure store-bandwidth bound.
// ---------------------------------------------------------------------------
__global__ __launch_bounds__(QUADS)
void il_main_kernel(const float* __restrict__ x,
                    const float* __restrict__ W,
                    const float* __restrict__ B,
                    const float* __restrict__ G,
                    const float* __restrict__ Be,
                    float* __restrict__ out,
                    int nrows) {
    const float SCALE = 32.0f;                 // sqrt(1024)
    const float S2 = SCALE * SCALE;

    int q = threadIdx.x;                       // 0..255
    int d0 = q * 4;
    int row0 = blockIdx.x * RPB;

    // Preload this block's x values into shared memory.
    __shared__ float xa[RPB];
    if (q < RPB) {
        int r = row0 + q;
        xa[q] = (r < nrows) ? x[r] : 0.0f;
    }

    float4 w4  = *(const float4*)(W  + d0);
    float4 b4  = *(const float4*)(B  + d0);
    float4 g4  = *(const float4*)(G  + d0);
    float4 be4 = *(const float4*)(Be + d0);

    float mw = g_stats[0], mb = g_stats[1];
    float vw = g_stats[2], vb = g_stats[3], cv = g_stats[4];

    // P = (W - meanW) * gamma ;  Q = (B - meanB) * gamma
    float4 P, Q;
    P.x = (w4.x - mw) * g4.x;  Q.x = (b4.x - mb) * g4.x;
    P.y = (w4.y - mw) * g4.y;  Q.y = (b4.y - mb) * g4.y;
    P.z = (w4.z - mw) * g4.z;  Q.z = (b4.z - mb) * g4.z;
    P.w = (w4.w - mw) * g4.w;  Q.w = (b4.w - mb) * g4.w;

    __syncthreads();

    int rmax = nrows - row0;
    if (rmax > RPB) rmax = RPB;

    #pragma unroll 4
    for (int r = 0; r < rmax; r++) {
        float a = xa[r];
        // var = S^2 * (a^2*varW + 2a*cov + varB)
        float var = S2 * fmaf(a, fmaf(a, vw, 2.0f * cv), vb);
        float t = SCALE * rsqrtf(var + LN_EPS);
        float c0 = t * a;

        float4 o;
        o.x = fmaf(c0, P.x, fmaf(t, Q.x, be4.x));
        o.y = fmaf(c0, P.y, fmaf(t, Q.y, be4.y));
        o.z = fmaf(c0, P.z, fmaf(t, Q.z, be4.z));
        o.w = fmaf(c0, P.w, fmaf(t, Q.w, be4.w));

        *(float4*)(out + (size_t)(row0 + r) * SIZE + d0) = o;
    }
}

extern "C" void kernel_launch(void* const* d_in, const int* in_sizes, int n_in,
                              void* d_out, int out_size) {
    const float* x  = (const float*)d_in[0];   // (2048, 32)
    const float* W  = (const float*)d_in[1];   // (1024, 1)
    const float* B  = (const float*)d_in[2];   // (1024,)
    const float* G  = (const float*)d_in[3];   // (1024,)
    const float* Be = (const float*)d_in[4];   // (1024,)
    float* out = (float*)d_out;

    int nrows = in_sizes[0];                   // 2048*32 = 65536 rows

    il_stats_kernel<<<1, SIZE>>>(W, B);

    int grid = (nrows + RPB - 1) / RPB;
    il_main_kernel<<<grid, QUADS>>>(x, W, B, G, Be, out, nrows);
}

// round 3
// speedup vs baseline: 1.4603x; 1.4603x over previous
#include <cuda_runtime.h>
#include <math.h>

// InputLayer: out[b,n,d] = LN_d( (x[b,n]*W[d] + bias[d]) * sqrt(1024) ) * gamma[d] + beta[d]
// Analytic LayerNorm: h is affine in a=x[b,n], so mean/var are closed-form in
// per-column stats of (W, bias). Single fused kernel: each block computes the
// tiny W/b stats itself (redundantly, from L2), then streams FMA + STG.128.

#define SIZE 1024
#define QUADS (SIZE / 4)          // 256 threads per block
#define RPB 64                    // rows per block
#define LN_EPS 1e-5f

__global__ __launch_bounds__(QUADS)
void il_fused_kernel(const float* __restrict__ x,
                     const float* __restrict__ W,
                     const float* __restrict__ B,
                     const float* __restrict__ G,
                     const float* __restrict__ Be,
                     float* __restrict__ out,
                     int nrows) {
    const float SCALE = 32.0f;                 // sqrt(1024)
    const float S2 = SCALE * SCALE;

    int q = threadIdx.x;                       // 0..255
    int d0 = q * 4;
    int row0 = blockIdx.x * RPB;

    __shared__ float xa[RPB];
    __shared__ float red[5][8];                // 5 stats x 8 warps

    if (q < RPB) {
        int r = row0 + q;
        xa[q] = (r < nrows) ? x[r] : 0.0f;
    }

    float4 w4  = *(const float4*)(W  + d0);
    float4 b4  = *(const float4*)(B  + d0);
    float4 g4  = *(const float4*)(G  + d0);
    float4 be4 = *(const float4*)(Be + d0);

    // ---- per-block stats reduction over the 1024 (W,b) columns ----
    float s0 = w4.x + w4.y + w4.z + w4.w;                              // sum W
    float s1 = b4.x + b4.y + b4.z + b4.w;                              // sum B
    float s2 = w4.x*w4.x + w4.y*w4.y + w4.z*w4.z + w4.w*w4.w;          // sum W^2
    float s3 = b4.x*b4.x + b4.y*b4.y + b4.z*b4.z + b4.w*b4.w;          // sum B^2
    float s4 = w4.x*b4.x + w4.y*b4.y + w4.z*b4.z + w4.w*b4.w;          // sum W*B

    int lane = q & 31, warp = q >> 5;
    #pragma unroll
    for (int o = 16; o > 0; o >>= 1) {
        s0 += __shfl_down_sync(0xffffffffu, s0, o);
        s1 += __shfl_down_sync(0xffffffffu, s1, o);
        s2 += __shfl_down_sync(0xffffffffu, s2, o);
        s3 += __shfl_down_sync(0xffffffffu, s3, o);
        s4 += __shfl_down_sync(0xffffffffu, s4, o);
    }
    if (lane == 0) {
        red[0][warp] = s0; red[1][warp] = s1; red[2][warp] = s2;
        red[3][warp] = s3; red[4][warp] = s4;
    }
    __syncthreads();

    float t0 = 0.f, t1 = 0.f, t2 = 0.f, t3 = 0.f, t4 = 0.f;
    #pragma unroll
    for (int i = 0; i < 8; i++) {
        t0 += red[0][i]; t1 += red[1][i]; t2 += red[2][i];
        t3 += red[3][i]; t4 += red[4][i];
    }
    const float inv = 1.0f / (float)SIZE;
    float mw = t0 * inv, mb = t1 * inv;
    float vw = fmaf(-mw, mw, t2 * inv);        // Var(W)
    float vb = fmaf(-mb, mb, t3 * inv);        // Var(B)
    float cv = fmaf(-mw, mb, t4 * inv);        // Cov(W,B)

    // P = (W - meanW) * gamma ;  Q = (B - meanB) * gamma
    float4 P, Q;
    P.x = (w4.x - mw) * g4.x;  Q.x = (b4.x - mb) * g4.x;
    P.y = (w4.y - mw) * g4.y;  Q.y = (b4.y - mb) * g4.y;
    P.z = (w4.z - mw) * g4.z;  Q.z = (b4.z - mb) * g4.z;
    P.w = (w4.w - mw) * g4.w;  Q.w = (b4.w - mb) * g4.w;

    int rmax = nrows - row0;
    if (rmax > RPB) rmax = RPB;

    float4* obase = (float4*)(out + (size_t)row0 * SIZE + d0);

    #pragma unroll 4
    for (int r = 0; r < rmax; r++) {
        float a = xa[r];
        float var = S2 * fmaf(a, fmaf(a, vw, 2.0f * cv), vb);
        float t = SCALE * rsqrtf(var + LN_EPS);
        float c0 = t * a;

        float4 o;
        o.x = fmaf(c0, P.x, fmaf(t, Q.x, be4.x));
        o.y = fmaf(c0, P.y, fmaf(t, Q.y, be4.y));
        o.z = fmaf(c0, P.z, fmaf(t, Q.z, be4.z));
        o.w = fmaf(c0, P.w, fmaf(t, Q.w, be4.w));

        // streaming store: output is never re-read
        __stcs(obase + (size_t)r * QUADS, o);
    }
}

extern "C" void kernel_launch(void* const* d_in, const int* in_sizes, int n_in,
                              void* d_out, int out_size) {
    const float* x  = (const float*)d_in[0];   // (2048, 32)
    const float* W  = (const float*)d_in[1];   // (1024, 1)
    const float* B  = (const float*)d_in[2];   // (1024,)
    const float* G  = (const float*)d_in[3];   // (1024,)
    const float* Be = (const float*)d_in[4];   // (1024,)
    float* out = (float*)d_out;

    int nrows = in_sizes[0];                   // 65536 rows

    int grid = (nrows + RPB - 1) / RPB;
    il_fused_kernel<<<grid, QUADS>>>(x, W, B, G, Be, out, nrows);
}